// round 1
// baseline (speedup 1.0000x reference)
#include <cuda_runtime.h>

// ConditionalAffineCoupling on GB300 — round 0 baseline (fp32 SIMT GEMMs).
//
// y, log_det = coupling(x, context):
//   st_in = [x[:, even] , context]            (B x 384)
//   h     = relu(st_in @ W1 + b1)             (B x 2048)
//   st    = h @ W2 + b2                       (B x 512)
//   s     = tanh(st[:, :256]) * 5
//   y[:, odd] = x[:, odd] * exp(s) + st[:, 256:]
//   y[:, even] = x[:, even]
//   log_det = sum(s, axis=1)
//
// Output layout: d_out[0 .. B*512)  = y (row-major)
//                d_out[B*512 .. B*513) = log_det

#define B_TOT 131072
#define DIM   512
#define CTXD  128
#define HID   2048
#define KIN   384   // D_M + CTX
#define DU    256

// Scratch for h (B x HID fp32) = 1 GiB. Static device array (allocation-free).
__device__ float g_h[(size_t)B_TOT * HID];

// ---------------------------------------------------------------------------
// GEMM1: h = relu(st_in @ W1 + b1).  M=B, N=HID, K=384.
// Tile: BM=64, BN=64, BK=16, 256 threads, 4x4 microtile.
// st_in is gathered on the fly from x (even cols) and context.
// ---------------------------------------------------------------------------
__global__ __launch_bounds__(256, 4)
void gemm1_kernel(const float* __restrict__ x,
                  const float* __restrict__ ctx,
                  const float* __restrict__ W1,
                  const float* __restrict__ b1)
{
    __shared__ float As[16][64];   // [k][row]
    __shared__ float Bs[16][64];   // [k][col]

    const int tid = threadIdx.x;
    const int bn0 = blockIdx.x * 64;
    const int bm0 = blockIdx.y * 64;
    const int tx  = tid & 15;      // 0..15 -> col group
    const int ty  = tid >> 4;      // 0..15 -> row group

    // A-load mapping: each thread loads 4 consecutive k for one row
    const int arow = tid >> 2;           // 0..63
    const int ak0  = (tid & 3) * 4;      // 0,4,8,12
    const size_t grow_a = (size_t)(bm0 + arow);

    // B-load mapping: each thread loads one float4 of W1
    const int bk = tid >> 4;             // 0..15
    const int bn = (tid & 15) * 4;

    float acc[4][4] = {};

    #pragma unroll 1
    for (int kt = 0; kt < KIN / 16; ++kt) {
        // ---- load st_in tile (gather) ----
        #pragma unroll
        for (int kk = 0; kk < 4; ++kk) {
            int kg = kt * 16 + ak0 + kk;
            float v;
            if (kg < 256) v = x[grow_a * DIM + 2 * kg];       // masked (even) cols
            else          v = ctx[grow_a * CTXD + (kg - 256)]; // context
            As[ak0 + kk][arow] = v;
        }
        // ---- load W1 tile ----
        float4 w = *(const float4*)&W1[(size_t)(kt * 16 + bk) * HID + bn0 + bn];
        *(float4*)&Bs[bk][bn] = w;
        __syncthreads();

        #pragma unroll
        for (int k = 0; k < 16; ++k) {
            float4 a4 = *(float4*)&As[k][ty * 4];
            float4 b4 = *(float4*)&Bs[k][tx * 4];
            float av[4] = {a4.x, a4.y, a4.z, a4.w};
            float bv[4] = {b4.x, b4.y, b4.z, b4.w};
            #pragma unroll
            for (int i = 0; i < 4; ++i)
                #pragma unroll
                for (int j = 0; j < 4; ++j)
                    acc[i][j] = fmaf(av[i], bv[j], acc[i][j]);
        }
        __syncthreads();
    }

    // ---- epilogue: +b1, relu, store h ----
    const int gcol = bn0 + tx * 4;
    float bb[4];
    #pragma unroll
    for (int j = 0; j < 4; ++j) bb[j] = b1[gcol + j];

    #pragma unroll
    for (int i = 0; i < 4; ++i) {
        size_t grow = (size_t)(bm0 + ty * 4 + i);
        float4 r;
        r.x = fmaxf(acc[i][0] + bb[0], 0.f);
        r.y = fmaxf(acc[i][1] + bb[1], 0.f);
        r.z = fmaxf(acc[i][2] + bb[2], 0.f);
        r.w = fmaxf(acc[i][3] + bb[3], 0.f);
        *(float4*)&g_h[grow * HID + gcol] = r;
    }
}

// ---------------------------------------------------------------------------
// GEMM2 + epilogue: st = h @ W2 + b2, then coupling + log_det.
// Tile: BM=32, BN=512 (full N so each CTA owns complete rows), BK=16,
// 256 threads. Thread (ty=tid/32, tx=tid%32) computes rows ty*4+i (i<4),
// cols {j4*128 + tx*4 + jj : j4<4, jj<4} -> 4x16 accum.
// Column pairing: col n (j4 in {0,1}) and col n+256 (j4+2) live in the SAME
// thread, so s/t pairing needs no exchange. Rows of a warp are owned entirely
// by that warp -> log_det via shfl reduction, no atomics.
// ---------------------------------------------------------------------------
__global__ __launch_bounds__(256, 2)
void gemm2_kernel(const float* __restrict__ x,
                  const float* __restrict__ W2,
                  const float* __restrict__ b2,
                  float* __restrict__ out)
{
    __shared__ float As[32][16];    // [row][k]
    __shared__ float Bs[16][512];   // [k][col]

    const int tid = threadIdx.x;
    const int bm0 = blockIdx.x * 32;
    const int tx  = tid & 31;   // lane
    const int ty  = tid >> 5;   // warp id, 0..7

    float acc[4][16] = {};

    #pragma unroll 1
    for (int kt = 0; kt < HID / 16; ++kt) {
        // ---- load h tile (32 rows x 16 k), threads 0..127 ----
        if (tid < 128) {
            int row = tid >> 2;
            int kq  = (tid & 3) * 4;
            float4 v = *(const float4*)&g_h[(size_t)(bm0 + row) * HID + kt * 16 + kq];
            *(float4*)&As[row][kq] = v;
        }
        // ---- load W2 tile (16 k x 512 n), all 256 threads ----
        {
            int nn = (tid & 127) * 4;
            int kb = tid >> 7;  // 0 or 1
            #pragma unroll
            for (int it = 0; it < 8; ++it) {
                int k = it * 2 + kb;
                *(float4*)&Bs[k][nn] =
                    *(const float4*)&W2[(size_t)(kt * 16 + k) * DIM + nn];
            }
        }
        __syncthreads();

        #pragma unroll
        for (int k = 0; k < 16; ++k) {
            float a[4];
            #pragma unroll
            for (int i = 0; i < 4; ++i) a[i] = As[ty * 4 + i][k];  // broadcast
            float4 bv[4];
            #pragma unroll
            for (int j4 = 0; j4 < 4; ++j4)
                bv[j4] = *(float4*)&Bs[k][j4 * 128 + tx * 4];      // conflict-free
            #pragma unroll
            for (int i = 0; i < 4; ++i) {
                #pragma unroll
                for (int j4 = 0; j4 < 4; ++j4) {
                    acc[i][j4 * 4 + 0] = fmaf(a[i], bv[j4].x, acc[i][j4 * 4 + 0]);
                    acc[i][j4 * 4 + 1] = fmaf(a[i], bv[j4].y, acc[i][j4 * 4 + 1]);
                    acc[i][j4 * 4 + 2] = fmaf(a[i], bv[j4].z, acc[i][j4 * 4 + 2]);
                    acc[i][j4 * 4 + 3] = fmaf(a[i], bv[j4].w, acc[i][j4 * 4 + 3]);
                }
            }
        }
        __syncthreads();
    }

    // ---- coupling epilogue ----
    float ld[4] = {0.f, 0.f, 0.f, 0.f};

    #pragma unroll
    for (int j4 = 0; j4 < 2; ++j4) {
        #pragma unroll
        for (int jj = 0; jj < 4; ++jj) {
            const int n  = j4 * 128 + tx * 4 + jj;   // s column (0..255)
            const float b_s = b2[n];
            const float b_t = b2[n + DU];
            #pragma unroll
            for (int i = 0; i < 4; ++i) {
                size_t grow = (size_t)(bm0 + ty * 4 + i);
                float s_raw = acc[i][j4 * 4 + jj] + b_s;
                float t_val = acc[i][(j4 + 2) * 4 + jj] + b_t;
                float s = tanhf(s_raw) * 5.0f;
                float2 xv = *(const float2*)&x[grow * DIM + 2 * n]; // (even, odd)
                float2 o;
                o.x = xv.x;                          // even col passthrough
                o.y = xv.y * expf(s) + t_val;        // odd col transformed
                *(float2*)&out[grow * DIM + 2 * n] = o;
                ld[i] += s;
            }
        }
    }

    // ---- log_det: warp owns its 4 rows entirely ----
    #pragma unroll
    for (int i = 0; i < 4; ++i) {
        float v = ld[i];
        #pragma unroll
        for (int off = 16; off > 0; off >>= 1)
            v += __shfl_xor_sync(0xffffffffu, v, off);
        if (tx == 0)
            out[(size_t)B_TOT * DIM + bm0 + ty * 4 + i] = v;
    }
}

// ---------------------------------------------------------------------------
// kernel_launch
// Inputs (metadata order): x(B*512), context(B*128), W1(384*2048), b1(2048),
//                          W2(2048*512), b2(512).
// Output: float, out_size = B*512 + B.
// ---------------------------------------------------------------------------
extern "C" void kernel_launch(void* const* d_in, const int* in_sizes, int n_in,
                              void* d_out, int out_size)
{
    const float* x   = (const float*)d_in[0];
    const float* ctx = (const float*)d_in[1];
    const float* W1  = (const float*)d_in[2];
    const float* b1  = (const float*)d_in[3];
    const float* W2  = (const float*)d_in[4];
    const float* b2  = (const float*)d_in[5];
    float* out = (float*)d_out;

    dim3 g1(HID / 64, B_TOT / 64);   // (32, 2048)
    gemm1_kernel<<<g1, 256>>>(x, ctx, W1, b1);

    dim3 g2(B_TOT / 32);             // 4096
    gemm2_kernel<<<g2, 256>>>(x, W2, b2, out);
}

// round 3
// speedup vs baseline: 3.0437x; 3.0437x over previous
#include <cuda_runtime.h>
#include <cuda_bf16.h>
#include <cstdint>

// ConditionalAffineCoupling — round 3: mma.sync (HMMA) bf16 hi/lo 3-term GEMMs.
// tcgen05 unavailable (toolchain targets sm_103 without 'a' features).

#define B_TOT 131072
#define DIM   512
#define CTXD  128
#define HID   2048
#define KIN   384

// ------------------------- device scratch (allocation-free) ----------------
__device__ __align__(1024) __nv_bfloat16 g_a1_hi[(size_t)B_TOT * KIN];
__device__ __align__(1024) __nv_bfloat16 g_a1_lo[(size_t)B_TOT * KIN];
__device__ __align__(1024) __nv_bfloat16 g_h_hi [(size_t)B_TOT * HID];
__device__ __align__(1024) __nv_bfloat16 g_h_lo [(size_t)B_TOT * HID];
__device__ __align__(1024) __nv_bfloat16 g_w1t_hi[(size_t)HID * KIN];
__device__ __align__(1024) __nv_bfloat16 g_w1t_lo[(size_t)HID * KIN];
__device__ __align__(1024) __nv_bfloat16 g_w2t_hi[(size_t)DIM * HID];
__device__ __align__(1024) __nv_bfloat16 g_w2t_lo[(size_t)DIM * HID];
__device__ __align__(1024) float         g_st   [(size_t)B_TOT * DIM];

// ------------------------- helpers -----------------------------------------
__device__ __forceinline__ uint32_t smem_u32(const void* p) {
    uint32_t a;
    asm("{ .reg .u64 t; cvta.to.shared.u64 t, %1; cvt.u32.u64 %0, t; }"
        : "=r"(a) : "l"(p));
    return a;
}
// SW64 swizzle for 64-byte rows (8-row atom), preserves 16B alignment.
__device__ __forceinline__ uint32_t swz64(uint32_t o) { return o ^ ((o >> 3) & 0x30); }

__device__ __forceinline__ void cp16(uint32_t sdst, const void* gsrc) {
    asm volatile("cp.async.cg.shared.global [%0], [%1], 16;"
                 :: "r"(sdst), "l"(gsrc));
}
__device__ __forceinline__ void ldsm4(uint32_t r[4], uint32_t addr) {
    asm volatile("ldmatrix.sync.aligned.m8n8.x4.shared.b16 {%0,%1,%2,%3}, [%4];"
                 : "=r"(r[0]), "=r"(r[1]), "=r"(r[2]), "=r"(r[3]) : "r"(addr));
}
__device__ __forceinline__ void ldsm2(uint32_t r[2], uint32_t addr) {
    asm volatile("ldmatrix.sync.aligned.m8n8.x2.shared.b16 {%0,%1}, [%2];"
                 : "=r"(r[0]), "=r"(r[1]) : "r"(addr));
}
__device__ __forceinline__ void mma16816(float c[4], const uint32_t a[4], const uint32_t b[2]) {
    asm volatile(
        "mma.sync.aligned.m16n8k16.row.col.f32.bf16.bf16.f32 "
        "{%0,%1,%2,%3}, {%4,%5,%6,%7}, {%8,%9}, {%0,%1,%2,%3};"
        : "+f"(c[0]), "+f"(c[1]), "+f"(c[2]), "+f"(c[3])
        : "r"(a[0]), "r"(a[1]), "r"(a[2]), "r"(a[3]), "r"(b[0]), "r"(b[1]));
}
__device__ __forceinline__ void split_bf16(float v, __nv_bfloat16& h, __nv_bfloat16& l) {
    h = __float2bfloat16(v);
    l = __float2bfloat16(v - __bfloat162float(h));
}

// ------------------------- prep kernels ------------------------------------
__global__ void prep_w1t(const float* __restrict__ W1) {
    int i = blockIdx.x * 256 + threadIdx.x;
    if (i >= HID * KIN) return;
    int n = i / KIN, k = i % KIN;
    split_bf16(W1[(size_t)k * HID + n], g_w1t_hi[i], g_w1t_lo[i]);
}
__global__ void prep_w2t(const float* __restrict__ W2) {
    int i = blockIdx.x * 256 + threadIdx.x;
    if (i >= DIM * HID) return;
    int n = i / HID, k = i % HID;
    split_bf16(W2[(size_t)k * DIM + n], g_w2t_hi[i], g_w2t_lo[i]);
}
__global__ void prep_a1(const float* __restrict__ x, const float* __restrict__ ctx) {
    size_t i = (size_t)blockIdx.x * 256 + threadIdx.x;
    if (i >= (size_t)B_TOT * KIN) return;
    int k = (int)(i % KIN);
    size_t row = i / KIN;
    float v = (k < 256) ? x[row * DIM + 2 * k] : ctx[row * CTXD + (k - 256)];
    split_bf16(v, g_a1_hi[i], g_a1_lo[i]);
}

// ------------------------- main GEMM (warp MMA, 3-term split) ---------------
// MODE 0: A=g_a1 (K=384),  B=g_w1t (2048xK); epi: relu(+b1) -> split -> g_h
// MODE 1: A=g_h  (K=2048), B=g_w2t (512xK);  epi: +b2 -> g_st (fp32)
// CTA: 128x128, BK=32 (64B), 3-stage cp.async pipeline, 8 warps of 64x32.
// SMEM per stage: Ah(8K) Al(8K) Bh(8K) Bl(8K) = 32KB; x3 stages = 96KB.
template <int MODE>
__global__ __launch_bounds__(256)
void gemm_mma(const float* __restrict__ bias)
{
    constexpr int KTOT   = MODE ? HID : KIN;
    constexpr int C      = KTOT / 32;
    constexpr int PITCH  = KTOT * 2;        // bytes per row (A and B^T K-major)
    constexpr int STAGE  = 32768;

    extern __shared__ char smem[];
    const uint32_t sb = smem_u32(smem);
    const int tid  = threadIdx.x, lane = tid & 31, wid = tid >> 5;
    const int wm   = wid >> 2;              // 0..1  (64-row slabs)
    const int wn   = wid & 3;               // 0..3  (32-col slabs)
    const int n0   = blockIdx.x * 128;
    const int bm0  = blockIdx.y * 128;

    const char* Ah = (const char*)(MODE ? g_h_hi   : g_a1_hi)  + (size_t)bm0 * PITCH;
    const char* Al = (const char*)(MODE ? g_h_lo   : g_a1_lo)  + (size_t)bm0 * PITCH;
    const char* Bh = (const char*)(MODE ? g_w2t_hi : g_w1t_hi) + (size_t)n0  * PITCH;
    const char* Bl = (const char*)(MODE ? g_w2t_lo : g_w1t_lo) + (size_t)n0  * PITCH;

    // per-thread loader task: 2 x (row, 16B-chunk) per region per stage
    const int r0c = tid >> 2, j0c = tid & 3;          // e = tid
    const int r1c = (tid + 256) >> 2, j1c = tid & 3;  // e = tid+256

    auto load_stage = [&](int s) {
        const uint32_t base = sb + (s % 3) * STAGE;
        const size_t kb = (size_t)s * 64;
        {
            uint32_t so = swz64((uint32_t)(r0c * 64 + j0c * 16));
            size_t go = (size_t)r0c * PITCH + kb + j0c * 16;
            cp16(base + so,         Ah + go);
            cp16(base + 8192 + so,  Al + go);
            cp16(base + 16384 + so, Bh + go);
            cp16(base + 24576 + so, Bl + go);
        }
        {
            uint32_t so = swz64((uint32_t)(r1c * 64 + j1c * 16));
            size_t go = (size_t)r1c * PITCH + kb + j1c * 16;
            cp16(base + so,         Ah + go);
            cp16(base + 8192 + so,  Al + go);
            cp16(base + 16384 + so, Bh + go);
            cp16(base + 24576 + so, Bl + go);
        }
    };

    // ldmatrix lane address components
    const int a_row  = wm * 64 + (lane & 15);       // + mt*16
    const int a_byte = (lane >> 4) * 16;            // + ks*32
    const int b_row  = wn * 32 + (lane & 7);        // + nt*8
    const int b_byte = ((lane >> 3) & 1) * 16;      // + ks*32  (lanes 0-15 used)

    float acc[4][4][4] = {};

    // prologue: stages 0,1
    load_stage(0);
    asm volatile("cp.async.commit_group;" ::: "memory");
    load_stage(1);
    asm volatile("cp.async.commit_group;" ::: "memory");

    #pragma unroll 1
    for (int c = 0; c < C; ++c) {
        if (c < C - 1) asm volatile("cp.async.wait_group 1;" ::: "memory");
        else           asm volatile("cp.async.wait_group 0;" ::: "memory");
        __syncthreads();

        if (c + 2 < C) {
            load_stage(c + 2);
            asm volatile("cp.async.commit_group;" ::: "memory");
        }

        const uint32_t stb = sb + (c % 3) * STAGE;
        #pragma unroll
        for (int ks = 0; ks < 2; ++ks) {
            uint32_t ah[4][4], al[4][4], bh[4][2], bl[4][2];
            #pragma unroll
            for (int nt = 0; nt < 4; ++nt) {
                uint32_t ad = stb + 16384 +
                    swz64((uint32_t)((b_row + nt * 8) * 64 + ks * 32 + b_byte));
                ldsm2(bh[nt], ad);
                ldsm2(bl[nt], ad + 8192);
            }
            #pragma unroll
            for (int mt = 0; mt < 4; ++mt) {
                uint32_t ad = stb +
                    swz64((uint32_t)((a_row + mt * 16) * 64 + ks * 32 + a_byte));
                ldsm4(ah[mt], ad);
                ldsm4(al[mt], ad + 8192);
            }
            #pragma unroll
            for (int mt = 0; mt < 4; ++mt)
                #pragma unroll
                for (int nt = 0; nt < 4; ++nt) {
                    mma16816(acc[mt][nt], ah[mt], bh[nt]);
                    mma16816(acc[mt][nt], ah[mt], bl[nt]);
                    mma16816(acc[mt][nt], al[mt], bh[nt]);
                }
        }
    }

    // ------------------------- epilogue -------------------------------------
    const int q = lane >> 2;                         // row-in-8
    const int npair = (lane & 3) * 2;

    if constexpr (MODE == 0) {
        #pragma unroll
        for (int nt = 0; nt < 4; ++nt) {
            const int gn = n0 + wn * 32 + nt * 8 + npair;
            const float bv0 = __ldg(bias + gn), bv1 = __ldg(bias + gn + 1);
            #pragma unroll
            for (int mt = 0; mt < 4; ++mt) {
                const int r0 = bm0 + wm * 64 + mt * 16 + q;
                float v00 = fmaxf(acc[mt][nt][0] + bv0, 0.f);
                float v01 = fmaxf(acc[mt][nt][1] + bv1, 0.f);
                float v10 = fmaxf(acc[mt][nt][2] + bv0, 0.f);
                float v11 = fmaxf(acc[mt][nt][3] + bv1, 0.f);
                __nv_bfloat16 h0, l0, h1, l1;
                split_bf16(v00, h0, l0); split_bf16(v01, h1, l1);
                uint32_t hi0 = (uint32_t)__bfloat16_as_ushort(h0) |
                               ((uint32_t)__bfloat16_as_ushort(h1) << 16);
                uint32_t lo0 = (uint32_t)__bfloat16_as_ushort(l0) |
                               ((uint32_t)__bfloat16_as_ushort(l1) << 16);
                split_bf16(v10, h0, l0); split_bf16(v11, h1, l1);
                uint32_t hi1 = (uint32_t)__bfloat16_as_ushort(h0) |
                               ((uint32_t)__bfloat16_as_ushort(h1) << 16);
                uint32_t lo1 = (uint32_t)__bfloat16_as_ushort(l0) |
                               ((uint32_t)__bfloat16_as_ushort(l1) << 16);
                *(uint32_t*)(g_h_hi + (size_t)r0 * HID + gn)       = hi0;
                *(uint32_t*)(g_h_lo + (size_t)r0 * HID + gn)       = lo0;
                *(uint32_t*)(g_h_hi + (size_t)(r0 + 8) * HID + gn) = hi1;
                *(uint32_t*)(g_h_lo + (size_t)(r0 + 8) * HID + gn) = lo1;
            }
        }
    } else {
        #pragma unroll
        for (int nt = 0; nt < 4; ++nt) {
            const int gn = n0 + wn * 32 + nt * 8 + npair;
            const float bv0 = __ldg(bias + gn), bv1 = __ldg(bias + gn + 1);
            #pragma unroll
            for (int mt = 0; mt < 4; ++mt) {
                const int r0 = bm0 + wm * 64 + mt * 16 + q;
                float2 v0 = make_float2(acc[mt][nt][0] + bv0, acc[mt][nt][1] + bv1);
                float2 v1 = make_float2(acc[mt][nt][2] + bv0, acc[mt][nt][3] + bv1);
                *(float2*)(g_st + (size_t)r0 * DIM + gn)       = v0;
                *(float2*)(g_st + (size_t)(r0 + 8) * DIM + gn) = v1;
            }
        }
    }
}

// ------------------------- coupling epilogue --------------------------------
__global__ __launch_bounds__(256)
void coupling_k(const float* __restrict__ x, float* __restrict__ out)
{
    const int row  = blockIdx.x * 8 + (threadIdx.x >> 5);
    const int lane = threadIdx.x & 31;
    const float* st = g_st + (size_t)row * DIM;
    const float* xr = x    + (size_t)row * DIM;
    float*       yr = out  + (size_t)row * DIM;
    float ldsum = 0.f;

    #pragma unroll
    for (int half = 0; half < 2; ++half) {
        float4 sv = *(const float4*)(st + lane * 8 + half * 4);
        float4 tv = *(const float4*)(st + 256 + lane * 8 + half * 4);
        float4 x0 = *(const float4*)(xr + lane * 16 + half * 8);
        float4 x1 = *(const float4*)(xr + lane * 16 + half * 8 + 4);
        float s[4]  = {sv.x, sv.y, sv.z, sv.w};
        float t[4]  = {tv.x, tv.y, tv.z, tv.w};
        float xe[4] = {x0.x, x0.z, x1.x, x1.z};
        float xo[4] = {x0.y, x0.w, x1.y, x1.w};
        float yo[4];
        #pragma unroll
        for (int i = 0; i < 4; ++i) {
            float e  = __expf(2.f * s[i]);
            float th = 1.f - 2.f / (e + 1.f);    // tanh, saturates correctly
            float sc = 5.f * th;
            ldsum += sc;
            yo[i] = xo[i] * __expf(sc) + t[i];
        }
        float4 o0 = make_float4(xe[0], yo[0], xe[1], yo[1]);
        float4 o1 = make_float4(xe[2], yo[2], xe[3], yo[3]);
        *(float4*)(yr + lane * 16 + half * 8)     = o0;
        *(float4*)(yr + lane * 16 + half * 8 + 4) = o1;
    }
    #pragma unroll
    for (int off = 16; off; off >>= 1)
        ldsum += __shfl_xor_sync(0xffffffffu, ldsum, off);
    if (lane == 0)
        out[(size_t)B_TOT * DIM + row] = ldsum;
}

// ------------------------- launch ------------------------------------------
extern "C" void kernel_launch(void* const* d_in, const int* in_sizes, int n_in,
                              void* d_out, int out_size)
{
    const float* x   = (const float*)d_in[0];
    const float* ctx = (const float*)d_in[1];
    const float* W1  = (const float*)d_in[2];
    const float* b1  = (const float*)d_in[3];
    const float* W2  = (const float*)d_in[4];
    const float* b2  = (const float*)d_in[5];
    float* out = (float*)d_out;

    cudaFuncSetAttribute(gemm_mma<0>, cudaFuncAttributeMaxDynamicSharedMemorySize, 98304);
    cudaFuncSetAttribute(gemm_mma<1>, cudaFuncAttributeMaxDynamicSharedMemorySize, 98304);

    prep_w1t<<<(HID * KIN + 255) / 256, 256>>>(W1);
    prep_w2t<<<(DIM * HID + 255) / 256, 256>>>(W2);
    prep_a1<<<(int)(((size_t)B_TOT * KIN + 255) / 256), 256>>>(x, ctx);

    gemm_mma<0><<<dim3(HID / 128, B_TOT / 128), 256, 98304>>>(b1);
    gemm_mma<1><<<dim3(DIM / 128, B_TOT / 128), 256, 98304>>>(b2);

    coupling_k<<<B_TOT / 8, 256>>>(x, out);
}

// round 4
// speedup vs baseline: 3.5811x; 1.1766x over previous
#include <cuda_runtime.h>
#include <cuda_bf16.h>
#include <cstdint>

// ConditionalAffineCoupling — round 4: HMMA bf16 3-term split, 2 CTAs/SM.

#define B_TOT 131072
#define DIM   512
#define CTXD  128
#define HID   2048
#define KIN   384

// ------------------------- device scratch (allocation-free) ----------------
__device__ __align__(1024) __nv_bfloat16 g_a1_hi[(size_t)B_TOT * KIN];
__device__ __align__(1024) __nv_bfloat16 g_a1_lo[(size_t)B_TOT * KIN];
__device__ __align__(1024) __nv_bfloat16 g_h_hi [(size_t)B_TOT * HID];
__device__ __align__(1024) __nv_bfloat16 g_h_lo [(size_t)B_TOT * HID];
__device__ __align__(1024) __nv_bfloat16 g_w1t_hi[(size_t)HID * KIN];
__device__ __align__(1024) __nv_bfloat16 g_w1t_lo[(size_t)HID * KIN];
__device__ __align__(1024) __nv_bfloat16 g_w2t_hi[(size_t)DIM * HID];
__device__ __align__(1024) __nv_bfloat16 g_w2t_lo[(size_t)DIM * HID];
__device__ __align__(1024) float         g_st   [(size_t)B_TOT * DIM];

// ------------------------- helpers -----------------------------------------
__device__ __forceinline__ uint32_t smem_u32(const void* p) {
    uint32_t a;
    asm("{ .reg .u64 t; cvta.to.shared.u64 t, %1; cvt.u32.u64 %0, t; }"
        : "=r"(a) : "l"(p));
    return a;
}
// SW64 swizzle for 64-byte rows (8-row atom), preserves 16B alignment.
__device__ __forceinline__ uint32_t swz64(uint32_t o) { return o ^ ((o >> 3) & 0x30); }

__device__ __forceinline__ void cp16(uint32_t sdst, const void* gsrc) {
    asm volatile("cp.async.cg.shared.global [%0], [%1], 16;"
                 :: "r"(sdst), "l"(gsrc));
}
__device__ __forceinline__ void ldsm4(uint32_t r[4], uint32_t addr) {
    asm volatile("ldmatrix.sync.aligned.m8n8.x4.shared.b16 {%0,%1,%2,%3}, [%4];"
                 : "=r"(r[0]), "=r"(r[1]), "=r"(r[2]), "=r"(r[3]) : "r"(addr));
}
__device__ __forceinline__ void ldsm2(uint32_t r[2], uint32_t addr) {
    asm volatile("ldmatrix.sync.aligned.m8n8.x2.shared.b16 {%0,%1}, [%2];"
                 : "=r"(r[0]), "=r"(r[1]) : "r"(addr));
}
__device__ __forceinline__ void mma16816(float c[4], const uint32_t a[4], const uint32_t b[2]) {
    asm volatile(
        "mma.sync.aligned.m16n8k16.row.col.f32.bf16.bf16.f32 "
        "{%0,%1,%2,%3}, {%4,%5,%6,%7}, {%8,%9}, {%0,%1,%2,%3};"
        : "+f"(c[0]), "+f"(c[1]), "+f"(c[2]), "+f"(c[3])
        : "r"(a[0]), "r"(a[1]), "r"(a[2]), "r"(a[3]), "r"(b[0]), "r"(b[1]));
}
__device__ __forceinline__ void split_bf16(float v, __nv_bfloat16& h, __nv_bfloat16& l) {
    h = __float2bfloat16(v);
    l = __float2bfloat16(v - __bfloat162float(h));
}

// ------------------------- prep kernels ------------------------------------
__global__ void prep_w1t(const float* __restrict__ W1) {
    int i = blockIdx.x * 256 + threadIdx.x;
    if (i >= HID * KIN) return;
    int n = i / KIN, k = i % KIN;
    split_bf16(W1[(size_t)k * HID + n], g_w1t_hi[i], g_w1t_lo[i]);
}
__global__ void prep_w2t(const float* __restrict__ W2) {
    int i = blockIdx.x * 256 + threadIdx.x;
    if (i >= DIM * HID) return;
    int n = i / HID, k = i % HID;
    split_bf16(W2[(size_t)k * DIM + n], g_w2t_hi[i], g_w2t_lo[i]);
}
__global__ void prep_a1(const float* __restrict__ x, const float* __restrict__ ctx) {
    size_t i = (size_t)blockIdx.x * 256 + threadIdx.x;
    if (i >= (size_t)B_TOT * KIN) return;
    int k = (int)(i % KIN);
    size_t row = i / KIN;
    float v = (k < 256) ? x[row * DIM + 2 * k] : ctx[row * CTXD + (k - 256)];
    split_bf16(v, g_a1_hi[i], g_a1_lo[i]);
}

// ------------------------- main GEMM (warp MMA, 3-term split) ---------------
// MODE 0: A=g_a1 (K=384),  B=g_w1t (2048xK); epi: relu(+b1) -> split -> g_h
// MODE 1: A=g_h  (K=2048), B=g_w2t (512xK);  epi: +b2 -> g_st (fp32)
// CTA: 128x128, BK=32 (64B), 3-stage cp.async pipeline, 8 warps of 64x32.
// SMEM per stage: Ah(8K) Al(8K) Bh(8K) Bl(8K) = 32KB; x3 stages = 96KB.
// __launch_bounds__(256, 2): 2 CTAs/SM (regs capped at 128; smem 192KB/SM).
template <int MODE>
__global__ __launch_bounds__(256, 2)
void gemm_mma(const float* __restrict__ bias)
{
    constexpr int KTOT   = MODE ? HID : KIN;
    constexpr int C      = KTOT / 32;
    constexpr int PITCH  = KTOT * 2;        // bytes per row (A and B^T K-major)
    constexpr int STAGE  = 32768;

    extern __shared__ char smem[];
    const uint32_t sb = smem_u32(smem);
    const int tid  = threadIdx.x, lane = tid & 31, wid = tid >> 5;
    const int wm   = wid >> 2;              // 0..1  (64-row slabs)
    const int wn   = wid & 3;               // 0..3  (32-col slabs)
    const int n0   = blockIdx.x * 128;
    const int bm0  = blockIdx.y * 128;

    const char* Ah = (const char*)(MODE ? g_h_hi   : g_a1_hi)  + (size_t)bm0 * PITCH;
    const char* Al = (const char*)(MODE ? g_h_lo   : g_a1_lo)  + (size_t)bm0 * PITCH;
    const char* Bh = (const char*)(MODE ? g_w2t_hi : g_w1t_hi) + (size_t)n0  * PITCH;
    const char* Bl = (const char*)(MODE ? g_w2t_lo : g_w1t_lo) + (size_t)n0  * PITCH;

    // per-thread loader task: 2 x (row, 16B-chunk) per region per stage
    const int r0c = tid >> 2, j0c = tid & 3;          // e = tid
    const int r1c = (tid + 256) >> 2, j1c = tid & 3;  // e = tid+256

    auto load_stage = [&](int s) {
        const uint32_t base = sb + (s % 3) * STAGE;
        const size_t kb = (size_t)s * 64;
        {
            uint32_t so = swz64((uint32_t)(r0c * 64 + j0c * 16));
            size_t go = (size_t)r0c * PITCH + kb + j0c * 16;
            cp16(base + so,         Ah + go);
            cp16(base + 8192 + so,  Al + go);
            cp16(base + 16384 + so, Bh + go);
            cp16(base + 24576 + so, Bl + go);
        }
        {
            uint32_t so = swz64((uint32_t)(r1c * 64 + j1c * 16));
            size_t go = (size_t)r1c * PITCH + kb + j1c * 16;
            cp16(base + so,         Ah + go);
            cp16(base + 8192 + so,  Al + go);
            cp16(base + 16384 + so, Bh + go);
            cp16(base + 24576 + so, Bl + go);
        }
    };

    // ldmatrix lane address components
    const int a_row  = wm * 64 + (lane & 15);       // + mt*16
    const int a_byte = (lane >> 4) * 16;            // + ks*32
    const int b_row  = wn * 32 + (lane & 7);        // + nt*8
    const int b_byte = ((lane >> 3) & 1) * 16;      // + ks*32  (lanes 0-15 used)

    float acc[4][4][4] = {};

    // prologue: stages 0,1
    load_stage(0);
    asm volatile("cp.async.commit_group;" ::: "memory");
    load_stage(1);
    asm volatile("cp.async.commit_group;" ::: "memory");

    #pragma unroll 1
    for (int c = 0; c < C; ++c) {
        if (c < C - 1) asm volatile("cp.async.wait_group 1;" ::: "memory");
        else           asm volatile("cp.async.wait_group 0;" ::: "memory");
        __syncthreads();

        if (c + 2 < C) {
            load_stage(c + 2);
            asm volatile("cp.async.commit_group;" ::: "memory");
        }

        const uint32_t stb = sb + (c % 3) * STAGE;
        #pragma unroll
        for (int ks = 0; ks < 2; ++ks) {
            // B fragments for all 4 n-tiles (16 regs), live across mt loop.
            uint32_t bh[4][2], bl[4][2];
            #pragma unroll
            for (int nt = 0; nt < 4; ++nt) {
                uint32_t ad = stb + 16384 +
                    swz64((uint32_t)((b_row + nt * 8) * 64 + ks * 32 + b_byte));
                ldsm2(bh[nt], ad);
                ldsm2(bl[nt], ad + 8192);
            }
            // Per m-tile: load 8 A regs, consume immediately (term-major over
            // nt -> accumulator dependency distance 4).
            #pragma unroll
            for (int mt = 0; mt < 4; ++mt) {
                uint32_t ah[4], al[4];
                uint32_t ad = stb +
                    swz64((uint32_t)((a_row + mt * 16) * 64 + ks * 32 + a_byte));
                ldsm4(ah, ad);
                ldsm4(al, ad + 8192);
                #pragma unroll
                for (int nt = 0; nt < 4; ++nt) mma16816(acc[mt][nt], ah, bh[nt]);
                #pragma unroll
                for (int nt = 0; nt < 4; ++nt) mma16816(acc[mt][nt], ah, bl[nt]);
                #pragma unroll
                for (int nt = 0; nt < 4; ++nt) mma16816(acc[mt][nt], al, bh[nt]);
            }
        }
    }

    // ------------------------- epilogue -------------------------------------
    const int q = lane >> 2;                         // row-in-8
    const int npair = (lane & 3) * 2;

    if constexpr (MODE == 0) {
        #pragma unroll
        for (int nt = 0; nt < 4; ++nt) {
            const int gn = n0 + wn * 32 + nt * 8 + npair;
            const float bv0 = __ldg(bias + gn), bv1 = __ldg(bias + gn + 1);
            #pragma unroll
            for (int mt = 0; mt < 4; ++mt) {
                const int r0 = bm0 + wm * 64 + mt * 16 + q;
                float v00 = fmaxf(acc[mt][nt][0] + bv0, 0.f);
                float v01 = fmaxf(acc[mt][nt][1] + bv1, 0.f);
                float v10 = fmaxf(acc[mt][nt][2] + bv0, 0.f);
                float v11 = fmaxf(acc[mt][nt][3] + bv1, 0.f);
                __nv_bfloat16 h0, l0, h1, l1;
                split_bf16(v00, h0, l0); split_bf16(v01, h1, l1);
                uint32_t hi0 = (uint32_t)__bfloat16_as_ushort(h0) |
                               ((uint32_t)__bfloat16_as_ushort(h1) << 16);
                uint32_t lo0 = (uint32_t)__bfloat16_as_ushort(l0) |
                               ((uint32_t)__bfloat16_as_ushort(l1) << 16);
                split_bf16(v10, h0, l0); split_bf16(v11, h1, l1);
                uint32_t hi1 = (uint32_t)__bfloat16_as_ushort(h0) |
                               ((uint32_t)__bfloat16_as_ushort(h1) << 16);
                uint32_t lo1 = (uint32_t)__bfloat16_as_ushort(l0) |
                               ((uint32_t)__bfloat16_as_ushort(l1) << 16);
                *(uint32_t*)(g_h_hi + (size_t)r0 * HID + gn)       = hi0;
                *(uint32_t*)(g_h_lo + (size_t)r0 * HID + gn)       = lo0;
                *(uint32_t*)(g_h_hi + (size_t)(r0 + 8) * HID + gn) = hi1;
                *(uint32_t*)(g_h_lo + (size_t)(r0 + 8) * HID + gn) = lo1;
            }
        }
    } else {
        #pragma unroll
        for (int nt = 0; nt < 4; ++nt) {
            const int gn = n0 + wn * 32 + nt * 8 + npair;
            const float bv0 = __ldg(bias + gn), bv1 = __ldg(bias + gn + 1);
            #pragma unroll
            for (int mt = 0; mt < 4; ++mt) {
                const int r0 = bm0 + wm * 64 + mt * 16 + q;
                float2 v0 = make_float2(acc[mt][nt][0] + bv0, acc[mt][nt][1] + bv1);
                float2 v1 = make_float2(acc[mt][nt][2] + bv0, acc[mt][nt][3] + bv1);
                *(float2*)(g_st + (size_t)r0 * DIM + gn)       = v0;
                *(float2*)(g_st + (size_t)(r0 + 8) * DIM + gn) = v1;
            }
        }
    }
}

// ------------------------- coupling epilogue --------------------------------
__global__ __launch_bounds__(256)
void coupling_k(const float* __restrict__ x, float* __restrict__ out)
{
    const int row  = blockIdx.x * 8 + (threadIdx.x >> 5);
    const int lane = threadIdx.x & 31;
    const float* st = g_st + (size_t)row * DIM;
    const float* xr = x    + (size_t)row * DIM;
    float*       yr = out  + (size_t)row * DIM;
    float ldsum = 0.f;

    #pragma unroll
    for (int half = 0; half < 2; ++half) {
        float4 sv = *(const float4*)(st + lane * 8 + half * 4);
        float4 tv = *(const float4*)(st + 256 + lane * 8 + half * 4);
        float4 x0 = *(const float4*)(xr + lane * 16 + half * 8);
        float4 x1 = *(const float4*)(xr + lane * 16 + half * 8 + 4);
        float s[4]  = {sv.x, sv.y, sv.z, sv.w};
        float t[4]  = {tv.x, tv.y, tv.z, tv.w};
        float xe[4] = {x0.x, x0.z, x1.x, x1.z};
        float xo[4] = {x0.y, x0.w, x1.y, x1.w};
        float yo[4];
        #pragma unroll
        for (int i = 0; i < 4; ++i) {
            float e  = __expf(2.f * s[i]);
            float th = 1.f - 2.f / (e + 1.f);    // tanh, saturates correctly
            float sc = 5.f * th;
            ldsum += sc;
            yo[i] = xo[i] * __expf(sc) + t[i];
        }
        float4 o0 = make_float4(xe[0], yo[0], xe[1], yo[1]);
        float4 o1 = make_float4(xe[2], yo[2], xe[3], yo[3]);
        *(float4*)(yr + lane * 16 + half * 8)     = o0;
        *(float4*)(yr + lane * 16 + half * 8 + 4) = o1;
    }
    #pragma unroll
    for (int off = 16; off; off >>= 1)
        ldsum += __shfl_xor_sync(0xffffffffu, ldsum, off);
    if (lane == 0)
        out[(size_t)B_TOT * DIM + row] = ldsum;
}

// ------------------------- launch ------------------------------------------
extern "C" void kernel_launch(void* const* d_in, const int* in_sizes, int n_in,
                              void* d_out, int out_size)
{
    const float* x   = (const float*)d_in[0];
    const float* ctx = (const float*)d_in[1];
    const float* W1  = (const float*)d_in[2];
    const float* b1  = (const float*)d_in[3];
    const float* W2  = (const float*)d_in[4];
    const float* b2  = (const float*)d_in[5];
    float* out = (float*)d_out;

    cudaFuncSetAttribute(gemm_mma<0>, cudaFuncAttributeMaxDynamicSharedMemorySize, 98304);
    cudaFuncSetAttribute(gemm_mma<1>, cudaFuncAttributeMaxDynamicSharedMemorySize, 98304);

    prep_w1t<<<(HID * KIN + 255) / 256, 256>>>(W1);
    prep_w2t<<<(DIM * HID + 255) / 256, 256>>>(W2);
    prep_a1<<<(int)(((size_t)B_TOT * KIN + 255) / 256), 256>>>(x, ctx);

    gemm_mma<0><<<dim3(HID / 128, B_TOT / 128), 256, 98304>>>(b1);
    gemm_mma<1><<<dim3(DIM / 128, B_TOT / 128), 256, 98304>>>(b2);

    coupling_k<<<B_TOT / 8, 256>>>(x, out);
}

// round 5
// speedup vs baseline: 5.5418x; 1.5475x over previous
#include <cuda_runtime.h>
#include <cuda_fp16.h>
#include <cstdint>

// ConditionalAffineCoupling — round 5: fp16 2-term split (A single fp16,
// weights split fp16 hi+lo), HMMA m16n8k16.f32.f16.f16.f32, 4-stage pipeline.

#define B_TOT 131072
#define DIM   512
#define CTXD  128
#define HID   2048
#define KIN   384

// ------------------------- device scratch (allocation-free) ----------------
__device__ __align__(1024) __half g_a1   [(size_t)B_TOT * KIN];
__device__ __align__(1024) __half g_h    [(size_t)B_TOT * HID];
__device__ __align__(1024) __half g_w1t_hi[(size_t)HID * KIN];
__device__ __align__(1024) __half g_w1t_lo[(size_t)HID * KIN];
__device__ __align__(1024) __half g_w2t_hi[(size_t)DIM * HID];
__device__ __align__(1024) __half g_w2t_lo[(size_t)DIM * HID];
__device__ __align__(1024) float  g_st   [(size_t)B_TOT * DIM];

// ------------------------- helpers -----------------------------------------
__device__ __forceinline__ uint32_t smem_u32(const void* p) {
    uint32_t a;
    asm("{ .reg .u64 t; cvta.to.shared.u64 t, %1; cvt.u32.u64 %0, t; }"
        : "=r"(a) : "l"(p));
    return a;
}
// SW64 swizzle for 64-byte rows (8-row atom), preserves 16B alignment.
__device__ __forceinline__ uint32_t swz64(uint32_t o) { return o ^ ((o >> 3) & 0x30); }

__device__ __forceinline__ void cp16(uint32_t sdst, const void* gsrc) {
    asm volatile("cp.async.cg.shared.global [%0], [%1], 16;"
                 :: "r"(sdst), "l"(gsrc));
}
__device__ __forceinline__ void ldsm4(uint32_t r[4], uint32_t addr) {
    asm volatile("ldmatrix.sync.aligned.m8n8.x4.shared.b16 {%0,%1,%2,%3}, [%4];"
                 : "=r"(r[0]), "=r"(r[1]), "=r"(r[2]), "=r"(r[3]) : "r"(addr));
}
__device__ __forceinline__ void mma16816(float c[4], const uint32_t a[4], const uint32_t b[2]) {
    asm volatile(
        "mma.sync.aligned.m16n8k16.row.col.f32.f16.f16.f32 "
        "{%0,%1,%2,%3}, {%4,%5,%6,%7}, {%8,%9}, {%0,%1,%2,%3};"
        : "+f"(c[0]), "+f"(c[1]), "+f"(c[2]), "+f"(c[3])
        : "r"(a[0]), "r"(a[1]), "r"(a[2]), "r"(a[3]), "r"(b[0]), "r"(b[1]));
}
__device__ __forceinline__ void split_fp16(float v, __half& h, __half& l) {
    h = __float2half(v);
    l = __float2half(v - __half2float(h));
}

// ------------------------- prep kernels ------------------------------------
__global__ void prep_w1t(const float* __restrict__ W1) {
    int i = blockIdx.x * 256 + threadIdx.x;
    if (i >= HID * KIN) return;
    int n = i / KIN, k = i % KIN;
    split_fp16(W1[(size_t)k * HID + n], g_w1t_hi[i], g_w1t_lo[i]);
}
__global__ void prep_w2t(const float* __restrict__ W2) {
    int i = blockIdx.x * 256 + threadIdx.x;
    if (i >= DIM * HID) return;
    int n = i / HID, k = i % HID;
    split_fp16(W2[(size_t)k * DIM + n], g_w2t_hi[i], g_w2t_lo[i]);
}
__global__ void prep_a1(const float* __restrict__ x, const float* __restrict__ ctx) {
    size_t i = (size_t)blockIdx.x * 256 + threadIdx.x;
    if (i >= (size_t)B_TOT * KIN) return;
    int k = (int)(i % KIN);
    size_t row = i / KIN;
    float v = (k < 256) ? x[row * DIM + 2 * k] : ctx[row * CTXD + (k - 256)];
    g_a1[i] = __float2half(v);
}

// ------------------------- main GEMM (warp MMA, 2-term split) ---------------
// MODE 0: A=g_a1 (K=384),  B=g_w1t hi/lo (2048xK); epi: relu(+b1) -> g_h fp16
// MODE 1: A=g_h  (K=2048), B=g_w2t hi/lo (512xK);  epi: +b2 -> g_st fp32
// CTA 128x128, BK=32 (64B rows), 4-stage cp.async pipeline, 8 warps of 64x32.
// Stage smem: A 8KB | Bh 8KB | Bl 8KB = 24KB; x4 stages = 96KB.
template <int MODE>
__global__ __launch_bounds__(256, 2)
void gemm_mma(const float* __restrict__ bias)
{
    constexpr int KTOT   = MODE ? HID : KIN;
    constexpr int C      = KTOT / 32;
    constexpr int PITCH  = KTOT * 2;        // bytes per row (A and B^T K-major)
    constexpr int STAGE  = 24576;

    extern __shared__ char smem[];
    const uint32_t sb = smem_u32(smem);
    const int tid  = threadIdx.x, lane = tid & 31, wid = tid >> 5;
    const int wm   = wid >> 2;              // 0..1  (64-row slabs)
    const int wn   = wid & 3;               // 0..3  (32-col slabs)
    const int n0   = blockIdx.x * 128;
    const int bm0  = blockIdx.y * 128;

    const char* A  = (const char*)(MODE ? g_h      : g_a1)     + (size_t)bm0 * PITCH;
    const char* Bh = (const char*)(MODE ? g_w2t_hi : g_w1t_hi) + (size_t)n0  * PITCH;
    const char* Bl = (const char*)(MODE ? g_w2t_lo : g_w1t_lo) + (size_t)n0  * PITCH;

    // loader: 128 rows x 4 chunks(16B) per region; 2 tasks/thread/region
    const int r0c = tid >> 2, j0c = (tid & 3) * 16;
    const int r1c = (tid + 256) >> 2;

    auto load_stage = [&](int s) {
        const uint32_t base = sb + (s & 3) * STAGE;
        const size_t kb = (size_t)s * 64;
        uint32_t so0 = swz64((uint32_t)(r0c * 64 + j0c));
        uint32_t so1 = swz64((uint32_t)(r1c * 64 + j0c));
        size_t go0 = (size_t)r0c * PITCH + kb + j0c;
        size_t go1 = (size_t)r1c * PITCH + kb + j0c;
        cp16(base + so0,          A  + go0);
        cp16(base + so1,          A  + go1);
        cp16(base + 8192  + so0,  Bh + go0);
        cp16(base + 8192  + so1,  Bh + go1);
        cp16(base + 16384 + so0,  Bl + go0);
        cp16(base + 16384 + so1,  Bl + go1);
    };

    // ldmatrix lane address components
    const int a_row  = wm * 64 + (lane & 15);          // + mt*16
    const int a_byte = (lane >> 4) * 16;               // + ks*32
    const int b_l8   = lane & 7;
    const int b_grp  = lane >> 3;                      // 0..3
    // x4 B load for pair p covers nt=2p (k0,k1) and nt=2p+1 (k0,k1)
    const int b_row0 = wn * 32 + (b_grp >> 1) * 8 + b_l8;   // + p*16
    const int b_byte = (b_grp & 1) * 16;                    // + ks*32

    float acc[4][4][4] = {};

    // prologue: stages 0,1,2
    load_stage(0); asm volatile("cp.async.commit_group;" ::: "memory");
    load_stage(1); asm volatile("cp.async.commit_group;" ::: "memory");
    load_stage(2); asm volatile("cp.async.commit_group;" ::: "memory");

    #pragma unroll 1
    for (int c = 0; c < C; ++c) {
        if (c < C - 3) asm volatile("cp.async.wait_group 2;" ::: "memory");
        else           asm volatile("cp.async.wait_group 0;" ::: "memory");
        __syncthreads();

        if (c + 3 < C) {
            load_stage(c + 3);
            asm volatile("cp.async.commit_group;" ::: "memory");
        }

        const uint32_t stb = sb + (c & 3) * STAGE;
        #pragma unroll
        for (int ks = 0; ks < 2; ++ks) {
            // B fragments: 2x ldsm4 per hi/lo cover all 4 n-tiles
            uint32_t bh[4][2], bl[4][2];
            #pragma unroll
            for (int p = 0; p < 2; ++p) {
                uint32_t r4[4];
                uint32_t ad = stb + 8192 +
                    swz64((uint32_t)((b_row0 + p * 16) * 64 + ks * 32 + b_byte));
                ldsm4(r4, ad);
                bh[2 * p][0] = r4[0]; bh[2 * p][1] = r4[1];
                bh[2 * p + 1][0] = r4[2]; bh[2 * p + 1][1] = r4[3];
                ldsm4(r4, ad + 8192);
                bl[2 * p][0] = r4[0]; bl[2 * p][1] = r4[1];
                bl[2 * p + 1][0] = r4[2]; bl[2 * p + 1][1] = r4[3];
            }
            #pragma unroll
            for (int mt = 0; mt < 4; ++mt) {
                uint32_t ah[4];
                ldsm4(ah, stb +
                    swz64((uint32_t)((a_row + mt * 16) * 64 + ks * 32 + a_byte)));
                #pragma unroll
                for (int nt = 0; nt < 4; ++nt) mma16816(acc[mt][nt], ah, bh[nt]);
                #pragma unroll
                for (int nt = 0; nt < 4; ++nt) mma16816(acc[mt][nt], ah, bl[nt]);
            }
        }
    }

    // ------------------------- epilogue -------------------------------------
    const int q = lane >> 2;                         // row-in-8
    const int npair = (lane & 3) * 2;

    if constexpr (MODE == 0) {
        #pragma unroll
        for (int nt = 0; nt < 4; ++nt) {
            const int gn = n0 + wn * 32 + nt * 8 + npair;
            const float bv0 = __ldg(bias + gn), bv1 = __ldg(bias + gn + 1);
            #pragma unroll
            for (int mt = 0; mt < 4; ++mt) {
                const int r0 = bm0 + wm * 64 + mt * 16 + q;
                __half2 v0 = __floats2half2_rn(fmaxf(acc[mt][nt][0] + bv0, 0.f),
                                               fmaxf(acc[mt][nt][1] + bv1, 0.f));
                __half2 v1 = __floats2half2_rn(fmaxf(acc[mt][nt][2] + bv0, 0.f),
                                               fmaxf(acc[mt][nt][3] + bv1, 0.f));
                *(__half2*)(g_h + (size_t)r0 * HID + gn)       = v0;
                *(__half2*)(g_h + (size_t)(r0 + 8) * HID + gn) = v1;
            }
        }
    } else {
        #pragma unroll
        for (int nt = 0; nt < 4; ++nt) {
            const int gn = n0 + wn * 32 + nt * 8 + npair;
            const float bv0 = __ldg(bias + gn), bv1 = __ldg(bias + gn + 1);
            #pragma unroll
            for (int mt = 0; mt < 4; ++mt) {
                const int r0 = bm0 + wm * 64 + mt * 16 + q;
                float2 v0 = make_float2(acc[mt][nt][0] + bv0, acc[mt][nt][1] + bv1);
                float2 v1 = make_float2(acc[mt][nt][2] + bv0, acc[mt][nt][3] + bv1);
                *(float2*)(g_st + (size_t)r0 * DIM + gn)       = v0;
                *(float2*)(g_st + (size_t)(r0 + 8) * DIM + gn) = v1;
            }
        }
    }
}

// ------------------------- coupling epilogue --------------------------------
__global__ __launch_bounds__(256)
void coupling_k(const float* __restrict__ x, float* __restrict__ out)
{
    const int row  = blockIdx.x * 8 + (threadIdx.x >> 5);
    const int lane = threadIdx.x & 31;
    const float* st = g_st + (size_t)row * DIM;
    const float* xr = x    + (size_t)row * DIM;
    float*       yr = out  + (size_t)row * DIM;
    float ldsum = 0.f;

    #pragma unroll
    for (int half = 0; half < 2; ++half) {
        float4 sv = *(const float4*)(st + lane * 8 + half * 4);
        float4 tv = *(const float4*)(st + 256 + lane * 8 + half * 4);
        float4 x0 = *(const float4*)(xr + lane * 16 + half * 8);
        float4 x1 = *(const float4*)(xr + lane * 16 + half * 8 + 4);
        float s[4]  = {sv.x, sv.y, sv.z, sv.w};
        float t[4]  = {tv.x, tv.y, tv.z, tv.w};
        float xe[4] = {x0.x, x0.z, x1.x, x1.z};
        float xo[4] = {x0.y, x0.w, x1.y, x1.w};
        float yo[4];
        #pragma unroll
        for (int i = 0; i < 4; ++i) {
            float e  = __expf(2.f * s[i]);
            float th = 1.f - 2.f / (e + 1.f);    // tanh, saturates correctly
            float sc = 5.f * th;
            ldsum += sc;
            yo[i] = xo[i] * __expf(sc) + t[i];
        }
        float4 o0 = make_float4(xe[0], yo[0], xe[1], yo[1]);
        float4 o1 = make_float4(xe[2], yo[2], xe[3], yo[3]);
        *(float4*)(yr + lane * 16 + half * 8)     = o0;
        *(float4*)(yr + lane * 16 + half * 8 + 4) = o1;
    }
    #pragma unroll
    for (int off = 16; off; off >>= 1)
        ldsum += __shfl_xor_sync(0xffffffffu, ldsum, off);
    if (lane == 0)
        out[(size_t)B_TOT * DIM + row] = ldsum;
}

// ------------------------- launch ------------------------------------------
extern "C" void kernel_launch(void* const* d_in, const int* in_sizes, int n_in,
                              void* d_out, int out_size)
{
    const float* x   = (const float*)d_in[0];
    const float* ctx = (const float*)d_in[1];
    const float* W1  = (const float*)d_in[2];
    const float* b1  = (const float*)d_in[3];
    const float* W2  = (const float*)d_in[4];
    const float* b2  = (const float*)d_in[5];
    float* out = (float*)d_out;

    cudaFuncSetAttribute(gemm_mma<0>, cudaFuncAttributeMaxDynamicSharedMemorySize, 98304);
    cudaFuncSetAttribute(gemm_mma<1>, cudaFuncAttributeMaxDynamicSharedMemorySize, 98304);

    prep_w1t<<<(HID * KIN + 255) / 256, 256>>>(W1);
    prep_w2t<<<(DIM * HID + 255) / 256, 256>>>(W2);
    prep_a1<<<(int)(((size_t)B_TOT * KIN + 255) / 256), 256>>>(x, ctx);

    gemm_mma<0><<<dim3(HID / 128, B_TOT / 128), 256, 98304>>>(b1);
    gemm_mma<1><<<dim3(DIM / 128, B_TOT / 128), 256, 98304>>>(b2);

    coupling_k<<<B_TOT / 8, 256>>>(x, out);
}

// round 6
// speedup vs baseline: 9.3530x; 1.6877x over previous
#include <cuda_runtime.h>
#include <cuda_fp16.h>
#include <cstdint>

// ConditionalAffineCoupling — round 6: single fp16 x fp16 HMMA (no split),
// BK=64, SW128, 3-stage cp.async pipeline, 2 CTAs/SM.

#define B_TOT 131072
#define DIM   512
#define CTXD  128
#define HID   2048
#define KIN   384

// ------------------------- device scratch (allocation-free) ----------------
__device__ __align__(1024) __half g_a1 [(size_t)B_TOT * KIN];
__device__ __align__(1024) __half g_h  [(size_t)B_TOT * HID];
__device__ __align__(1024) __half g_w1t[(size_t)HID * KIN];
__device__ __align__(1024) __half g_w2t[(size_t)DIM * HID];
__device__ __align__(1024) float  g_st [(size_t)B_TOT * DIM];

// ------------------------- helpers -----------------------------------------
__device__ __forceinline__ uint32_t smem_u32(const void* p) {
    uint32_t a;
    asm("{ .reg .u64 t; cvta.to.shared.u64 t, %1; cvt.u32.u64 %0, t; }"
        : "=r"(a) : "l"(p));
    return a;
}
// SW128 swizzle for 128-byte rows (8-row atom), preserves 16B alignment.
__device__ __forceinline__ uint32_t swz128(uint32_t o) { return o ^ ((o >> 3) & 0x70); }

__device__ __forceinline__ void cp16(uint32_t sdst, const void* gsrc) {
    asm volatile("cp.async.cg.shared.global [%0], [%1], 16;"
                 :: "r"(sdst), "l"(gsrc));
}
__device__ __forceinline__ void ldsm4(uint32_t r[4], uint32_t addr) {
    asm volatile("ldmatrix.sync.aligned.m8n8.x4.shared.b16 {%0,%1,%2,%3}, [%4];"
                 : "=r"(r[0]), "=r"(r[1]), "=r"(r[2]), "=r"(r[3]) : "r"(addr));
}
__device__ __forceinline__ void mma16816(float c[4], const uint32_t a[4], const uint32_t b[2]) {
    asm volatile(
        "mma.sync.aligned.m16n8k16.row.col.f32.f16.f16.f32 "
        "{%0,%1,%2,%3}, {%4,%5,%6,%7}, {%8,%9}, {%0,%1,%2,%3};"
        : "+f"(c[0]), "+f"(c[1]), "+f"(c[2]), "+f"(c[3])
        : "r"(a[0]), "r"(a[1]), "r"(a[2]), "r"(a[3]), "r"(b[0]), "r"(b[1]));
}

// ------------------------- prep kernels ------------------------------------
__global__ void prep_w1t(const float* __restrict__ W1) {
    int i = blockIdx.x * 256 + threadIdx.x;
    if (i >= HID * KIN) return;
    int n = i / KIN, k = i % KIN;
    g_w1t[i] = __float2half(W1[(size_t)k * HID + n]);
}
__global__ void prep_w2t(const float* __restrict__ W2) {
    int i = blockIdx.x * 256 + threadIdx.x;
    if (i >= DIM * HID) return;
    int n = i / HID, k = i % HID;
    g_w2t[i] = __float2half(W2[(size_t)k * DIM + n]);
}
__global__ void prep_a1(const float* __restrict__ x, const float* __restrict__ ctx) {
    size_t i = (size_t)blockIdx.x * 256 + threadIdx.x;
    if (i >= (size_t)B_TOT * KIN) return;
    int k = (int)(i % KIN);
    size_t row = i / KIN;
    float v = (k < 256) ? x[row * DIM + 2 * k] : ctx[row * CTXD + (k - 256)];
    g_a1[i] = __float2half(v);
}

// ------------------------- main GEMM (single-term fp16 warp MMA) ------------
// MODE 0: A=g_a1 (K=384),  B=g_w1t (2048xK); epi: relu(+b1) -> g_h fp16
// MODE 1: A=g_h  (K=2048), B=g_w2t (512xK);  epi: +b2 -> g_st fp32
// CTA 128x128, BK=64 (128B rows, SW128), 3-stage cp.async, 8 warps of 64x32.
// Stage smem: A 16KB | B 16KB = 32KB; x3 stages = 96KB.
template <int MODE>
__global__ __launch_bounds__(256, 2)
void gemm_mma(const float* __restrict__ bias)
{
    constexpr int KTOT   = MODE ? HID : KIN;
    constexpr int C      = KTOT / 64;
    constexpr int PITCH  = KTOT * 2;        // bytes per row (A and B^T K-major)
    constexpr int STAGE  = 32768;

    extern __shared__ char smem[];
    const uint32_t sb = smem_u32(smem);
    const int tid  = threadIdx.x, lane = tid & 31, wid = tid >> 5;
    const int wm   = wid >> 2;              // 0..1  (64-row slabs)
    const int wn   = wid & 3;               // 0..3  (32-col slabs)
    const int n0   = blockIdx.x * 128;
    const int bm0  = blockIdx.y * 128;

    const char* A = (const char*)(MODE ? g_h   : g_a1)  + (size_t)bm0 * PITCH;
    const char* B = (const char*)(MODE ? g_w2t : g_w1t) + (size_t)n0  * PITCH;

    // loader: each region 128 rows x 8 chunks(16B) = 1024 cp16; 4/thread/region
    const int lrow = tid >> 3, lchk = (tid & 7) * 16;

    auto load_stage = [&](int s) {
        const uint32_t base = sb + (s % 3) * STAGE;
        const size_t kb = (size_t)s * 128;
        #pragma unroll
        for (int i = 0; i < 4; ++i) {
            int r = lrow + i * 32;
            uint32_t so = swz128((uint32_t)(r * 128 + lchk));
            size_t go = (size_t)r * PITCH + kb + lchk;
            cp16(base + so,         A + go);
            cp16(base + 16384 + so, B + go);
        }
    };

    // ldmatrix lane address components
    const int a_row  = wm * 64 + (lane & 15);          // + mt*16
    const int a_byte = (lane >> 4) * 16;               // + ksub*32
    const int b_l8   = lane & 7;
    const int b_grp  = lane >> 3;                      // 0..3
    const int b_row0 = wn * 32 + (b_grp >> 1) * 8 + b_l8;   // + p*16
    const int b_byte = (b_grp & 1) * 16;                    // + ksub*32

    float acc[4][4][4] = {};

    load_stage(0); asm volatile("cp.async.commit_group;" ::: "memory");
    load_stage(1); asm volatile("cp.async.commit_group;" ::: "memory");

    #pragma unroll 1
    for (int c = 0; c < C; ++c) {
        if (c < C - 1) asm volatile("cp.async.wait_group 1;" ::: "memory");
        else           asm volatile("cp.async.wait_group 0;" ::: "memory");
        __syncthreads();

        if (c + 2 < C) {
            load_stage(c + 2);
            asm volatile("cp.async.commit_group;" ::: "memory");
        }

        const uint32_t stb = sb + (c % 3) * STAGE;
        #pragma unroll
        for (int ksub = 0; ksub < 4; ++ksub) {
            // B fragments: 2x ldsm4 cover all 4 n-tiles for this k16
            uint32_t bf[4][2];
            #pragma unroll
            for (int p = 0; p < 2; ++p) {
                uint32_t r4[4];
                ldsm4(r4, stb + 16384 +
                    swz128((uint32_t)((b_row0 + p * 16) * 128 + ksub * 32 + b_byte)));
                bf[2 * p][0] = r4[0]; bf[2 * p][1] = r4[1];
                bf[2 * p + 1][0] = r4[2]; bf[2 * p + 1][1] = r4[3];
            }
            #pragma unroll
            for (int mt = 0; mt < 4; ++mt) {
                uint32_t af[4];
                ldsm4(af, stb +
                    swz128((uint32_t)((a_row + mt * 16) * 128 + ksub * 32 + a_byte)));
                #pragma unroll
                for (int nt = 0; nt < 4; ++nt) mma16816(acc[mt][nt], af, bf[nt]);
            }
        }
    }

    // ------------------------- epilogue -------------------------------------
    const int q = lane >> 2;                         // row-in-8
    const int npair = (lane & 3) * 2;

    if constexpr (MODE == 0) {
        #pragma unroll
        for (int nt = 0; nt < 4; ++nt) {
            const int gn = n0 + wn * 32 + nt * 8 + npair;
            const float bv0 = __ldg(bias + gn), bv1 = __ldg(bias + gn + 1);
            #pragma unroll
            for (int mt = 0; mt < 4; ++mt) {
                const int r0 = bm0 + wm * 64 + mt * 16 + q;
                __half2 v0 = __floats2half2_rn(fmaxf(acc[mt][nt][0] + bv0, 0.f),
                                               fmaxf(acc[mt][nt][1] + bv1, 0.f));
                __half2 v1 = __floats2half2_rn(fmaxf(acc[mt][nt][2] + bv0, 0.f),
                                               fmaxf(acc[mt][nt][3] + bv1, 0.f));
                *(__half2*)(g_h + (size_t)r0 * HID + gn)       = v0;
                *(__half2*)(g_h + (size_t)(r0 + 8) * HID + gn) = v1;
            }
        }
    } else {
        #pragma unroll
        for (int nt = 0; nt < 4; ++nt) {
            const int gn = n0 + wn * 32 + nt * 8 + npair;
            const float bv0 = __ldg(bias + gn), bv1 = __ldg(bias + gn + 1);
            #pragma unroll
            for (int mt = 0; mt < 4; ++mt) {
                const int r0 = bm0 + wm * 64 + mt * 16 + q;
                float2 v0 = make_float2(acc[mt][nt][0] + bv0, acc[mt][nt][1] + bv1);
                float2 v1 = make_float2(acc[mt][nt][2] + bv0, acc[mt][nt][3] + bv1);
                *(float2*)(g_st + (size_t)r0 * DIM + gn)       = v0;
                *(float2*)(g_st + (size_t)(r0 + 8) * DIM + gn) = v1;
            }
        }
    }
}

// ------------------------- coupling epilogue --------------------------------
__global__ __launch_bounds__(256)
void coupling_k(const float* __restrict__ x, float* __restrict__ out)
{
    const int row  = blockIdx.x * 8 + (threadIdx.x >> 5);
    const int lane = threadIdx.x & 31;
    const float* st = g_st + (size_t)row * DIM;
    const float* xr = x    + (size_t)row * DIM;
    float*       yr = out  + (size_t)row * DIM;
    float ldsum = 0.f;

    #pragma unroll
    for (int half = 0; half < 2; ++half) {
        float4 sv = *(const float4*)(st + lane * 8 + half * 4);
        float4 tv = *(const float4*)(st + 256 + lane * 8 + half * 4);
        float4 x0 = *(const float4*)(xr + lane * 16 + half * 8);
        float4 x1 = *(const float4*)(xr + lane * 16 + half * 8 + 4);
        float s[4]  = {sv.x, sv.y, sv.z, sv.w};
        float t[4]  = {tv.x, tv.y, tv.z, tv.w};
        float xe[4] = {x0.x, x0.z, x1.x, x1.z};
        float xo[4] = {x0.y, x0.w, x1.y, x1.w};
        float yo[4];
        #pragma unroll
        for (int i = 0; i < 4; ++i) {
            float e  = __expf(2.f * s[i]);
            float th = 1.f - 2.f / (e + 1.f);    // tanh, saturates correctly
            float sc = 5.f * th;
            ldsum += sc;
            yo[i] = xo[i] * __expf(sc) + t[i];
        }
        float4 o0 = make_float4(xe[0], yo[0], xe[1], yo[1]);
        float4 o1 = make_float4(xe[2], yo[2], xe[3], yo[3]);
        *(float4*)(yr + lane * 16 + half * 8)     = o0;
        *(float4*)(yr + lane * 16 + half * 8 + 4) = o1;
    }
    #pragma unroll
    for (int off = 16; off; off >>= 1)
        ldsum += __shfl_xor_sync(0xffffffffu, ldsum, off);
    if (lane == 0)
        out[(size_t)B_TOT * DIM + row] = ldsum;
}

// ------------------------- launch ------------------------------------------
extern "C" void kernel_launch(void* const* d_in, const int* in_sizes, int n_in,
                              void* d_out, int out_size)
{
    const float* x   = (const float*)d_in[0];
    const float* ctx = (const float*)d_in[1];
    const float* W1  = (const float*)d_in[2];
    const float* b1  = (const float*)d_in[3];
    const float* W2  = (const float*)d_in[4];
    const float* b2  = (const float*)d_in[5];
    float* out = (float*)d_out;

    cudaFuncSetAttribute(gemm_mma<0>, cudaFuncAttributeMaxDynamicSharedMemorySize, 98304);
    cudaFuncSetAttribute(gemm_mma<1>, cudaFuncAttributeMaxDynamicSharedMemorySize, 98304);

    prep_w1t<<<(HID * KIN + 255) / 256, 256>>>(W1);
    prep_w2t<<<(DIM * HID + 255) / 256, 256>>>(W2);
    prep_a1<<<(int)(((size_t)B_TOT * KIN + 255) / 256), 256>>>(x, ctx);

    gemm_mma<0><<<dim3(HID / 128, B_TOT / 128), 256, 98304>>>(b1);
    gemm_mma<1><<<dim3(DIM / 128, B_TOT / 128), 256, 98304>>>(b2);

    coupling_k<<<B_TOT / 8, 256>>>(x, out);
}

// round 8
// speedup vs baseline: 9.6983x; 1.0369x over previous
#include <cuda_runtime.h>
#include <cuda_fp16.h>
#include <cstdint>

// ConditionalAffineCoupling — round 8: fp16 HMMA GEMMs, coupling fused into
// GEMM2 via interleaved W2 columns (s_j, t_j adjacent); deterministic log_det
// partials + tiny reduce kernel. Fix vs R7: g_b2i referenced from device code
// (a __device__ symbol must not be passed by name from host).

#define B_TOT 131072
#define DIM   512
#define CTXD  128
#define HID   2048
#define KIN   384

// ------------------------- device scratch (allocation-free) ----------------
__device__ __align__(1024) __half g_a1 [(size_t)B_TOT * KIN];
__device__ __align__(1024) __half g_h  [(size_t)B_TOT * HID];
__device__ __align__(1024) __half g_w1t[(size_t)HID * KIN];
__device__ __align__(1024) __half g_w2t[(size_t)DIM * HID];   // interleaved cols
__device__ __align__(1024) float  g_b2i[DIM];                 // interleaved bias
__device__ __align__(1024) float  g_ldp[4][B_TOT];            // log_det partials

// ------------------------- helpers -----------------------------------------
__device__ __forceinline__ uint32_t smem_u32(const void* p) {
    uint32_t a;
    asm("{ .reg .u64 t; cvta.to.shared.u64 t, %1; cvt.u32.u64 %0, t; }"
        : "=r"(a) : "l"(p));
    return a;
}
// SW128 swizzle for 128-byte rows (8-row atom), preserves 16B alignment.
__device__ __forceinline__ uint32_t swz128(uint32_t o) { return o ^ ((o >> 3) & 0x70); }

__device__ __forceinline__ void cp16(uint32_t sdst, const void* gsrc) {
    asm volatile("cp.async.cg.shared.global [%0], [%1], 16;"
                 :: "r"(sdst), "l"(gsrc));
}
__device__ __forceinline__ void ldsm4(uint32_t r[4], uint32_t addr) {
    asm volatile("ldmatrix.sync.aligned.m8n8.x4.shared.b16 {%0,%1,%2,%3}, [%4];"
                 : "=r"(r[0]), "=r"(r[1]), "=r"(r[2]), "=r"(r[3]) : "r"(addr));
}
__device__ __forceinline__ void mma16816(float c[4], const uint32_t a[4], const uint32_t b[2]) {
    asm volatile(
        "mma.sync.aligned.m16n8k16.row.col.f32.f16.f16.f32 "
        "{%0,%1,%2,%3}, {%4,%5,%6,%7}, {%8,%9}, {%0,%1,%2,%3};"
        : "+f"(c[0]), "+f"(c[1]), "+f"(c[2]), "+f"(c[3])
        : "r"(a[0]), "r"(a[1]), "r"(a[2]), "r"(a[3]), "r"(b[0]), "r"(b[1]));
}

// ------------------------- prep kernels ------------------------------------
__global__ void prep_w1t(const float* __restrict__ W1) {
    int i = blockIdx.x * 256 + threadIdx.x;
    if (i >= HID * KIN) return;
    int n = i / KIN, k = i % KIN;
    g_w1t[i] = __float2half(W1[(size_t)k * HID + n]);
}
// Interleave: new col 2j = old col j (s), new col 2j+1 = old col 256+j (t).
__global__ void prep_w2t(const float* __restrict__ W2, const float* __restrict__ b2) {
    int i = blockIdx.x * 256 + threadIdx.x;
    if (i < DIM) {
        int on = (i & 1) ? 256 + (i >> 1) : (i >> 1);
        g_b2i[i] = b2[on];
    }
    if (i >= DIM * HID) return;
    int n = i / HID, k = i % HID;
    int on = (n & 1) ? 256 + (n >> 1) : (n >> 1);
    g_w2t[i] = __float2half(W2[(size_t)k * DIM + on]);
}
__global__ void prep_a1(const float* __restrict__ x, const float* __restrict__ ctx) {
    size_t i = (size_t)blockIdx.x * 256 + threadIdx.x;
    if (i >= (size_t)B_TOT * KIN) return;
    int k = (int)(i % KIN);
    size_t row = i / KIN;
    float v = (k < 256) ? x[row * DIM + 2 * k] : ctx[row * CTXD + (k - 256)];
    g_a1[i] = __float2half(v);
}

// ------------------------- main GEMM (single-term fp16 warp MMA) ------------
// MODE 0: A=g_a1 (K=384),  B=g_w1t (2048xK); epi: relu(+b1) -> g_h fp16
// MODE 1: A=g_h  (K=2048), B=g_w2t (512xK, interleaved); epi: fused coupling
//         -> y (d_out) + log_det partials g_ldp[blockIdx.x][row]
// CTA 128x128, BK=64 (128B rows, SW128), 3-stage cp.async, 8 warps of 64x32.
// Stage smem: A 16KB | B 16KB = 32KB; x3 stages = 96KB.
template <int MODE>
__global__ __launch_bounds__(256, 2)
void gemm_mma(const float* __restrict__ bias_in,
              const float* __restrict__ x,
              float* __restrict__ out)
{
    constexpr int KTOT   = MODE ? HID : KIN;
    constexpr int C      = KTOT / 64;
    constexpr int PITCH  = KTOT * 2;        // bytes per row (A and B^T K-major)
    constexpr int STAGE  = 32768;

    // MODE 1 uses the interleaved-bias device symbol directly.
    const float* bias = MODE ? (const float*)g_b2i : bias_in;

    extern __shared__ char smem[];
    const uint32_t sb = smem_u32(smem);
    const int tid  = threadIdx.x, lane = tid & 31, wid = tid >> 5;
    const int wm   = wid >> 2;              // 0..1  (64-row slabs)
    const int wn   = wid & 3;               // 0..3  (32-col slabs)
    const int n0   = blockIdx.x * 128;
    const int bm0  = blockIdx.y * 128;

    const char* A = (const char*)(MODE ? g_h   : g_a1)  + (size_t)bm0 * PITCH;
    const char* B = (const char*)(MODE ? g_w2t : g_w1t) + (size_t)n0  * PITCH;

    // loader: each region 128 rows x 8 chunks(16B) = 1024 cp16; 4/thread/region
    const int lrow = tid >> 3, lchk = (tid & 7) * 16;

    auto load_stage = [&](int s) {
        const uint32_t base = sb + (s % 3) * STAGE;
        const size_t kb = (size_t)s * 128;
        #pragma unroll
        for (int i = 0; i < 4; ++i) {
            int r = lrow + i * 32;
            uint32_t so = swz128((uint32_t)(r * 128 + lchk));
            size_t go = (size_t)r * PITCH + kb + lchk;
            cp16(base + so,         A + go);
            cp16(base + 16384 + so, B + go);
        }
    };

    // ldmatrix lane address components
    const int a_row  = wm * 64 + (lane & 15);          // + mt*16
    const int a_byte = (lane >> 4) * 16;               // + ksub*32
    const int b_l8   = lane & 7;
    const int b_grp  = lane >> 3;                      // 0..3
    const int b_row0 = wn * 32 + (b_grp >> 1) * 8 + b_l8;   // + p*16
    const int b_byte = (b_grp & 1) * 16;                    // + ksub*32

    float acc[4][4][4] = {};

    load_stage(0); asm volatile("cp.async.commit_group;" ::: "memory");
    load_stage(1); asm volatile("cp.async.commit_group;" ::: "memory");

    #pragma unroll 1
    for (int c = 0; c < C; ++c) {
        if (c < C - 1) asm volatile("cp.async.wait_group 1;" ::: "memory");
        else           asm volatile("cp.async.wait_group 0;" ::: "memory");
        __syncthreads();

        if (c + 2 < C) {
            load_stage(c + 2);
            asm volatile("cp.async.commit_group;" ::: "memory");
        }

        const uint32_t stb = sb + (c % 3) * STAGE;
        #pragma unroll
        for (int ksub = 0; ksub < 4; ++ksub) {
            uint32_t bf[4][2];
            #pragma unroll
            for (int p = 0; p < 2; ++p) {
                uint32_t r4[4];
                ldsm4(r4, stb + 16384 +
                    swz128((uint32_t)((b_row0 + p * 16) * 128 + ksub * 32 + b_byte)));
                bf[2 * p][0] = r4[0]; bf[2 * p][1] = r4[1];
                bf[2 * p + 1][0] = r4[2]; bf[2 * p + 1][1] = r4[3];
            }
            #pragma unroll
            for (int mt = 0; mt < 4; ++mt) {
                uint32_t af[4];
                ldsm4(af, stb +
                    swz128((uint32_t)((a_row + mt * 16) * 128 + ksub * 32 + a_byte)));
                #pragma unroll
                for (int nt = 0; nt < 4; ++nt) mma16816(acc[mt][nt], af, bf[nt]);
            }
        }
    }

    // ------------------------- epilogue -------------------------------------
    const int q = lane >> 2;                         // row-in-8
    const int npair = (lane & 3) * 2;

    if constexpr (MODE == 0) {
        #pragma unroll
        for (int nt = 0; nt < 4; ++nt) {
            const int gn = n0 + wn * 32 + nt * 8 + npair;
            const float bv0 = __ldg(bias + gn), bv1 = __ldg(bias + gn + 1);
            #pragma unroll
            for (int mt = 0; mt < 4; ++mt) {
                const int r0 = bm0 + wm * 64 + mt * 16 + q;
                __half2 v0 = __floats2half2_rn(fmaxf(acc[mt][nt][0] + bv0, 0.f),
                                               fmaxf(acc[mt][nt][1] + bv1, 0.f));
                __half2 v1 = __floats2half2_rn(fmaxf(acc[mt][nt][2] + bv0, 0.f),
                                               fmaxf(acc[mt][nt][3] + bv1, 0.f));
                *(__half2*)(g_h + (size_t)r0 * HID + gn)       = v0;
                *(__half2*)(g_h + (size_t)(r0 + 8) * HID + gn) = v1;
            }
        }
    } else {
        // Fused coupling: acc pair (c0,c1) = (s_raw, t_raw) for column pair gn.
        float ldp[8] = {0.f, 0.f, 0.f, 0.f, 0.f, 0.f, 0.f, 0.f};
        #pragma unroll
        for (int nt = 0; nt < 4; ++nt) {
            const int gn = n0 + wn * 32 + nt * 8 + npair;
            const float bs = __ldg(bias + gn), bt = __ldg(bias + gn + 1);
            #pragma unroll
            for (int mt = 0; mt < 4; ++mt) {
                const int r0 = bm0 + wm * 64 + mt * 16 + q;
                #pragma unroll
                for (int hh = 0; hh < 2; ++hh) {
                    const int r = r0 + hh * 8;
                    float s_raw = acc[mt][nt][2 * hh]     + bs;
                    float t_val = acc[mt][nt][2 * hh + 1] + bt;
                    float e2 = __expf(2.f * s_raw);
                    float s  = 5.f * (1.f - 2.f / (e2 + 1.f));   // 5*tanh
                    ldp[mt * 2 + hh] += s;
                    float2 xv = *(const float2*)(x + (size_t)r * DIM + gn);
                    float2 o  = make_float2(xv.x, xv.y * __expf(s) + t_val);
                    *(float2*)(out + (size_t)r * DIM + gn) = o;
                }
            }
        }
        // quad reduce (lanes of a quad share the same rows)
        #pragma unroll
        for (int i = 0; i < 8; ++i) {
            ldp[i] += __shfl_xor_sync(0xffffffffu, ldp[i], 1);
            ldp[i] += __shfl_xor_sync(0xffffffffu, ldp[i], 2);
        }
        __syncthreads();                     // smem (stages) now reusable
        float* red = (float*)smem;           // [128 rows][4 wn]
        if ((lane & 3) == 0) {
            #pragma unroll
            for (int i = 0; i < 8; ++i) {
                int row_local = wm * 64 + (i >> 1) * 16 + q + (i & 1) * 8;
                red[row_local * 4 + wn] = ldp[i];
            }
        }
        __syncthreads();
        if (tid < 128) {
            float p = red[tid * 4] + red[tid * 4 + 1] +
                      red[tid * 4 + 2] + red[tid * 4 + 3];
            g_ldp[blockIdx.x][bm0 + tid] = p;
        }
    }
}

// ------------------------- log_det final reduce -----------------------------
__global__ __launch_bounds__(256)
void ldred(float* __restrict__ out)
{
    int r = blockIdx.x * 256 + threadIdx.x;
    out[(size_t)B_TOT * DIM + r] =
        g_ldp[0][r] + g_ldp[1][r] + g_ldp[2][r] + g_ldp[3][r];
}

// ------------------------- launch ------------------------------------------
extern "C" void kernel_launch(void* const* d_in, const int* in_sizes, int n_in,
                              void* d_out, int out_size)
{
    const float* x   = (const float*)d_in[0];
    const float* ctx = (const float*)d_in[1];
    const float* W1  = (const float*)d_in[2];
    const float* b1  = (const float*)d_in[3];
    const float* W2  = (const float*)d_in[4];
    const float* b2  = (const float*)d_in[5];
    float* out = (float*)d_out;

    cudaFuncSetAttribute(gemm_mma<0>, cudaFuncAttributeMaxDynamicSharedMemorySize, 98304);
    cudaFuncSetAttribute(gemm_mma<1>, cudaFuncAttributeMaxDynamicSharedMemorySize, 98304);

    prep_w1t<<<(HID * KIN + 255) / 256, 256>>>(W1);
    prep_w2t<<<(DIM * HID + 255) / 256, 256>>>(W2, b2);
    prep_a1<<<(int)(((size_t)B_TOT * KIN + 255) / 256), 256>>>(x, ctx);

    gemm_mma<0><<<dim3(HID / 128, B_TOT / 128), 256, 98304>>>(b1, nullptr, nullptr);
    gemm_mma<1><<<dim3(DIM / 128, B_TOT / 128), 256, 98304>>>(nullptr, x, out);

    ldred<<<B_TOT / 256, 256>>>(out);
}